// round 13
// baseline (speedup 1.0000x reference)
#include <cuda_runtime.h>
#include <cstdint>

#define NN 50000
#define NE 1200000
#define INC 128
#define HC 64
#define OC 64
#define SB 196                     // scan blocks (196*256 = 50176 >= NN)
#define GB 1563                    // gemm blocks ((NN+31)/32)
#define HB ((NE + 127) / 128)      // hist blocks at 128 threads
#define SCTB ((NE + 1023) / 1024)  // scatter blocks (4 edges/thread, 256 thr)

#define NEG_INF __int_as_float(0xff800000)

typedef unsigned long long ull;

// ---------------- scratch ----------------
__device__ __align__(16) float g_xl[(size_t)NN * HC];
__device__ __align__(16) float g_xr[(size_t)NN * HC];
__device__ __align__(16) float g_hid[(size_t)NN * HC];
__device__ __align__(16) float g_Wt[INC * 128];
__device__ __align__(16) float g_Wlt[HC * OC];
__device__ int   g_cnt[SB * 256];      // degree counts; zeroed by scan for next replay
__device__ int   g_off[NN + 1];
__device__ int   g_srcs[NE];
__device__ __align__(16) ull g_dr[NE]; // packed (dst<<16|src)<<32 | rank
__device__ int   g_flag[SB];           // lookback: 0=invalid 1=agg 2=inclusive
__device__ int   g_agg[SB];
__device__ int   g_incl[SB];
__device__ int   g_scan_done;
__device__ int   g_work;               // work-stealing node counter
__device__ int   g_probe;              // 1 => int32 storage, 0 => int64

// ---------------- helpers ----------------
__device__ __forceinline__ ull pack2(float lo, float hi) {
    ull r; asm("mov.b64 %0, {%1, %2};" : "=l"(r) : "f"(lo), "f"(hi)); return r;
}
__device__ __forceinline__ void unpack2(ull v, float& lo, float& hi) {
    asm("mov.b64 {%0, %1}, %2;" : "=f"(lo), "=f"(hi) : "l"(v));
}
__device__ __forceinline__ void ffma2(ull& d, ull a, ull b) {
    asm("fma.rn.f32x2 %0, %1, %2, %0;" : "+l"(d) : "l"(a), "l"(b));
}
__device__ __forceinline__ ull add2(ull a, ull b) {
    ull r; asm("add.rn.f32x2 %0, %1, %2;" : "=l"(r) : "l"(a), "l"(b)); return r;
}
__device__ __forceinline__ int load_idx(const void* ei, int pos, int is64) {
    int v = is64 ? (int)((const long long*)ei)[pos] : ((const int*)ei)[pos];
    return (v < 0) ? 0 : (v >= NN ? NN - 1 : v);
}

// ---------------- K0: weight transpose + dtype probe + control resets ----------------
__global__ void k_pre(const float* __restrict__ Wl, const float* __restrict__ Wr,
                      const float* __restrict__ Wlin, const int* __restrict__ ei32) {
    int t0 = blockIdx.x * blockDim.x + threadIdx.x;
    if (t0 < 32) {
        int v = 0;
#pragma unroll 8
        for (int it = 0; it < 32; it++) v |= ei32[2 * (t0 + 32 * it) + 1];
#pragma unroll
        for (int o = 16; o; o >>= 1) v |= __shfl_xor_sync(0xffffffffu, v, o);
        if (t0 == 0) { g_probe = (v != 0) ? 1 : 0; g_scan_done = 0; g_work = 0; }
    }
    if (t0 < SB) g_flag[t0] = 0;
    if (t0 < INC * 128) {
        int k = t0 >> 7, ch = t0 & 127;
        g_Wt[t0] = (ch < HC) ? Wl[ch * INC + k] : Wr[(ch - HC) * INC + k];
    }
    if (t0 < HC * OC) {
        int k = t0 >> 6, o = t0 & 63;
        g_Wlt[t0] = Wlin[o * HC + k];
    }
}

// ---------------- K1: MERGED projection GEMM + histogram/pack ----------------
__global__ void __launch_bounds__(128) k_gh(const float* __restrict__ x,
                                            const void* __restrict__ ei) {
    __shared__ __align__(16) float xs2[32 * INC];
    int tid = threadIdx.x;

    if (blockIdx.x >= GB) {
        int is64 = (g_probe == 0);
        int e = (blockIdx.x - GB) * 128 + tid;
        if (e < NE) {
            int d = load_idx(ei, NE + e, is64);
            int s = load_idx(ei, e, is64);
            int r = atomicAdd(&g_cnt[d], 1);
            g_dr[e] = ((ull)(((unsigned)d << 16) | (unsigned)s) << 32) | (unsigned)r;
        }
        return;
    }

    int row0 = blockIdx.x * 32;
    int nrows = NN - row0; if (nrows > 32) nrows = 32;

    for (int i = tid; i < 32 * (INC / 4); i += 128) {
        int r = i >> 5;
        int k4 = (i & 31) << 2;
        if (r < nrows) {
            float4 v = *(const float4*)(x + (size_t)(row0 + r) * INC + k4);
            float* b = xs2 + (r >> 1) * (2 * INC) + (r & 1);
            b[2 * k4 + 0] = v.x; b[2 * k4 + 2] = v.y;
            b[2 * k4 + 4] = v.z; b[2 * k4 + 6] = v.w;
        }
    }
    __syncthreads();

    int warp = tid >> 5, lane = tid & 31;
    int c = lane << 2;
    ull acc[4][4];
#pragma unroll
    for (int q = 0; q < 4; q++)
#pragma unroll
        for (int j = 0; j < 4; j++) acc[q][j] = 0ull;

    const float* xb = xs2 + (warp * 4) * (2 * INC);
#pragma unroll 8
    for (int k = 0; k < INC; k++) {
        float4 w = *(const float4*)(g_Wt + (k << 7) + c);
        ull w0 = pack2(w.x, w.x), w1 = pack2(w.y, w.y);
        ull w2 = pack2(w.z, w.z), w3 = pack2(w.w, w.w);
#pragma unroll
        for (int q = 0; q < 4; q++) {
            ull xp = *(const ull*)(xb + q * (2 * INC) + 2 * k);
            ffma2(acc[q][0], xp, w0);
            ffma2(acc[q][1], xp, w1);
            ffma2(acc[q][2], xp, w2);
            ffma2(acc[q][3], xp, w3);
        }
    }

    float* base = (c < HC) ? (g_xl + c) : (g_xr + (c - HC));
#pragma unroll
    for (int q = 0; q < 4; q++) {
        int re = row0 + warp * 8 + q * 2;
        if (re >= NN) break;
        float lo0, hi0, lo1, hi1, lo2, hi2, lo3, hi3;
        unpack2(acc[q][0], lo0, hi0); unpack2(acc[q][1], lo1, hi1);
        unpack2(acc[q][2], lo2, hi2); unpack2(acc[q][3], lo3, hi3);
        *(float4*)(base + (size_t)re * HC) = make_float4(lo0, lo1, lo2, lo3);
        if (re + 1 < NN)
            *(float4*)(base + (size_t)(re + 1) * HC) = make_float4(hi0, hi1, hi2, hi3);
    }
}

// ---------------- K2: MERGED decoupled-lookback scan + scatter ----------------
__global__ void __launch_bounds__(256) k_ss() {
    int tid = threadIdx.x;
    int b = blockIdx.x;

    if (b < SB) {
        __shared__ int wsum[8];
        __shared__ int s_base;
        int i = b * 256 + tid;
        int v = g_cnt[i];
        g_cnt[i] = 0;
        int lane = tid & 31, wid = tid >> 5;
        int xv = v;
#pragma unroll
        for (int o = 1; o < 32; o <<= 1) {
            int y = __shfl_up_sync(0xffffffffu, xv, o);
            if (lane >= o) xv += y;
        }
        if (lane == 31) wsum[wid] = xv;
        __syncthreads();
        if (tid < 8) {
            int w = wsum[tid];
#pragma unroll
            for (int o = 1; o < 8; o <<= 1) {
                int y = __shfl_up_sync(0x000000ffu, w, o);
                if (tid >= o) w += y;
            }
            wsum[tid] = w;
        }
        __syncthreads();
        int excl = xv - v + ((wid > 0) ? wsum[wid - 1] : 0);
        int T = wsum[7];

        if (b == 0) {
            if (tid == 0) {
                g_incl[0] = T;
                __threadfence();
                atomicExch(&g_flag[0], 2);
                s_base = 0;
            }
        } else if (tid < 32) {
            if (tid == 0) {
                g_agg[b] = T;
                __threadfence();
                atomicExch(&g_flag[b], 1);
            }
            __syncwarp();
            int sum = 0;
            int p = b - 1;
            for (;;) {
                int idx = p - tid;
                int f = 0;
                if (idx >= 0) {
                    do { f = atomicAdd(&g_flag[idx], 0); } while (f == 0);
                }
                unsigned m2 = __ballot_sync(0xffffffffu, (idx >= 0) && (f == 2));
                int kcut = m2 ? (__ffs(m2) - 1) : 32;
                __threadfence();
                int contrib = 0;
                if (idx >= 0 && tid <= kcut)
                    contrib = (tid == kcut) ? atomicAdd(&g_incl[idx], 0)
                                            : atomicAdd(&g_agg[idx], 0);
#pragma unroll
                for (int o = 16; o; o >>= 1) contrib += __shfl_xor_sync(0xffffffffu, contrib, o);
                sum += contrib;
                if (m2) break;
                p -= 32;
            }
            if (tid == 0) {
                g_incl[b] = sum + T;
                __threadfence();
                atomicExch(&g_flag[b], 2);
                s_base = sum;
            }
        }
        __syncthreads();
        if (i < NN) g_off[i] = excl + s_base;
        if (b == 0 && tid == 0) g_off[NN] = NE;
        __threadfence();
        __syncthreads();
        if (tid == 0) atomicAdd(&g_scan_done, 1);
        return;
    }

    if (tid == 0) {
        while (atomicAdd(&g_scan_done, 0) < SB) __nanosleep(64);
    }
    __syncthreads();
    __threadfence();

    int e0 = (b - SB) * 1024 + tid;
#pragma unroll
    for (int k = 0; k < 4; k++) {
        int e = e0 + k * 256;
        if (e < NE) {
            ull dr = g_dr[e];
            unsigned hi = (unsigned)(dr >> 32);
            int d = hi >> 16;
            int s = hi & 0xFFFF;
            int r = (int)(unsigned)dr;
            g_srcs[g_off[d] + r] = s;
        }
    }
}

// ---------------- K3: persistent work-stealing aggregation -> g_hid ----------------
// Epilogue GEMM removed (separate dense k_out amortizes weight loads over rows);
// k_aggr now ends at bias+ELU and writes h to g_hid (2 STG.128, quarter 0).
__global__ void __launch_bounds__(512, 2) k_aggr(const float* __restrict__ att,
                                                 const float* __restrict__ bias) {
    int tid = threadIdx.x;
    int lane = tid & 31;
    int quarter = lane >> 3, l8 = lane & 7;
    int c0 = l8 * 4, c1 = 32 + l8 * 4;

    // packed 0.6*att pairs, scalar 0.4*att
    float4 at0 = *(const float4*)(att + c0);
    float4 at1 = *(const float4*)(att + c1);
    ull a6p00 = pack2(0.6f * at0.x, 0.6f * at0.y);
    ull a6p01 = pack2(0.6f * at0.z, 0.6f * at0.w);
    ull a6p10 = pack2(0.6f * at1.x, 0.6f * at1.y);
    ull a6p11 = pack2(0.6f * at1.z, 0.6f * at1.w);
    float a40x = 0.4f * at0.x, a40y = 0.4f * at0.y, a40z = 0.4f * at0.z, a40w = 0.4f * at0.w;
    float a41x = 0.4f * at1.x, a41y = 0.4f * at1.y, a41z = 0.4f * at1.z, a41w = 0.4f * at1.w;

    for (;;) {
        int n;
        if (lane == 0) n = atomicAdd(&g_work, 1);
        n = __shfl_sync(0xffffffffu, n, 0);
        if (n >= NN) break;

        const float* xri = g_xr + ((unsigned)n << 6);
        ulonglong2 xrp0 = *(const ulonglong2*)(xri + c0);
        ulonglong2 xrp1 = *(const ulonglong2*)(xri + c1);

        // K = dot(a6, xr) for this lane's 8 channels
        ull kp = 0ull;
        ffma2(kp, xrp0.x, a6p00); ffma2(kp, xrp0.y, a6p01);
        ffma2(kp, xrp1.x, a6p10); ffma2(kp, xrp1.y, a6p11);
        float klo, khi; unpack2(kp, klo, khi);
        float K = klo + khi;

        ull accp[4] = {0ull, 0ull, 0ull, 0ull};
        float d;

        // ---- self loop (all quarters, 0.25 scale; merge tree sums exactly to 1x) ----
        const float* xli = g_xl + ((unsigned)n << 6);
        ulonglong2 v0p = *(const ulonglong2*)(xli + c0);
        ulonglong2 v1p = *(const ulonglong2*)(xli + c1);
        {
            ull sp = 0ull;
            ffma2(sp, v0p.x, a6p00); ffma2(sp, v0p.y, a6p01);
            ffma2(sp, v1p.x, a6p10); ffma2(sp, v1p.y, a6p11);
            ull u0 = add2(v0p.x, xrp0.x), u1 = add2(v0p.y, xrp0.y);
            ull u2 = add2(v1p.x, xrp1.x), u3 = add2(v1p.y, xrp1.y);
            float ul, uh, sa = K;
            unpack2(u0, ul, uh); sa = fmaf(fabsf(ul), a40x, sa); sa = fmaf(fabsf(uh), a40y, sa);
            unpack2(u1, ul, uh); sa = fmaf(fabsf(ul), a40z, sa); sa = fmaf(fabsf(uh), a40w, sa);
            unpack2(u2, ul, uh); sa = fmaf(fabsf(ul), a41x, sa); sa = fmaf(fabsf(uh), a41y, sa);
            unpack2(u3, ul, uh); sa = fmaf(fabsf(ul), a41z, sa); sa = fmaf(fabsf(uh), a41w, sa);
            float slo, shi; unpack2(sp, slo, shi);
            float s = sa + slo + shi;
            s += __shfl_xor_sync(0xffffffffu, s, 1);
            s += __shfl_xor_sync(0xffffffffu, s, 2);
            s += __shfl_xor_sync(0xffffffffu, s, 4);
            float pe = 0.25f * __expf(s);
            d = pe;
            ull pep = pack2(pe, pe);
            ffma2(accp[0], pep, v0p.x); ffma2(accp[1], pep, v0p.y);
            ffma2(accp[2], pep, v1p.x); ffma2(accp[3], pep, v1p.y);
        }

        // ---- edges: 4 in flight (one per quarter), src prefetch ----
        int off = g_off[n], end = g_off[n + 1];
        int my = off + quarter;
        bool vcur = (my < end);
        int jcur = vcur ? g_srcs[my] : n;
        for (int e = off; e < end; e += 4) {
            int myn = my + 4;
            bool vn = (myn < end);
            int jn = vn ? g_srcs[myn] : n;

            const float* vp = g_xl + ((unsigned)jcur << 6);
            v0p = *(const ulonglong2*)(vp + c0);
            v1p = *(const ulonglong2*)(vp + c1);
            ull sp = 0ull;
            ffma2(sp, v0p.x, a6p00); ffma2(sp, v0p.y, a6p01);
            ffma2(sp, v1p.x, a6p10); ffma2(sp, v1p.y, a6p11);
            ull u0 = add2(v0p.x, xrp0.x), u1 = add2(v0p.y, xrp0.y);
            ull u2 = add2(v1p.x, xrp1.x), u3 = add2(v1p.y, xrp1.y);
            float ul, uh, sa = K;
            unpack2(u0, ul, uh); sa = fmaf(fabsf(ul), a40x, sa); sa = fmaf(fabsf(uh), a40y, sa);
            unpack2(u1, ul, uh); sa = fmaf(fabsf(ul), a40z, sa); sa = fmaf(fabsf(uh), a40w, sa);
            unpack2(u2, ul, uh); sa = fmaf(fabsf(ul), a41x, sa); sa = fmaf(fabsf(uh), a41y, sa);
            unpack2(u3, ul, uh); sa = fmaf(fabsf(ul), a41z, sa); sa = fmaf(fabsf(uh), a41w, sa);
            float slo, shi; unpack2(sp, slo, shi);
            float s = sa + slo + shi;
            float q = vcur ? s : NEG_INF;
            q += __shfl_xor_sync(0xffffffffu, q, 1);
            q += __shfl_xor_sync(0xffffffffu, q, 2);
            q += __shfl_xor_sync(0xffffffffu, q, 4);
            float pe = __expf(q);               // 0 for invalid
            d += pe;
            ull pep = pack2(pe, pe);
            ffma2(accp[0], pep, v0p.x); ffma2(accp[1], pep, v0p.y);
            ffma2(accp[2], pep, v1p.x); ffma2(accp[3], pep, v1p.y);

            my = myn; vcur = vn; jcur = jn;
        }

        // unpack + merge quarters
        float acc[8];
        unpack2(accp[0], acc[0], acc[1]); unpack2(accp[1], acc[2], acc[3]);
        unpack2(accp[2], acc[4], acc[5]); unpack2(accp[3], acc[6], acc[7]);
        d += __shfl_xor_sync(0xffffffffu, d, 8);
        d += __shfl_xor_sync(0xffffffffu, d, 16);
#pragma unroll
        for (int k = 0; k < 8; k++) acc[k] += __shfl_xor_sync(0xffffffffu, acc[k], 8);
#pragma unroll
        for (int k = 0; k < 8; k++) acc[k] += __shfl_xor_sync(0xffffffffu, acc[k], 16);

        float inv = 1.0f / (d + 1e-16f);
        float4 b0 = *(const float4*)(bias + c0);
        float4 b1 = *(const float4*)(bias + c1);
        float h[8];
        h[0] = acc[0] * inv + b0.x; h[1] = acc[1] * inv + b0.y;
        h[2] = acc[2] * inv + b0.z; h[3] = acc[3] * inv + b0.w;
        h[4] = acc[4] * inv + b1.x; h[5] = acc[5] * inv + b1.y;
        h[6] = acc[6] * inv + b1.z; h[7] = acc[7] * inv + b1.w;
#pragma unroll
        for (int k = 0; k < 8; k++) h[k] = (h[k] > 0.0f) ? h[k] : expm1f(h[k]);

        if (quarter == 0) {
            float* hp = g_hid + ((size_t)n << 6);
            *(float4*)(hp + c0) = make_float4(h[0], h[1], h[2], h[3]);
            *(float4*)(hp + c1) = make_float4(h[4], h[5], h[6], h[7]);
        }
    }
}

// ---------------- K4: dense 64x64 output GEMM + bias (weights amortized over 8 rows) ----------------
__global__ void __launch_bounds__(128) k_out(const float* __restrict__ blin,
                                             float* __restrict__ out) {
    __shared__ __align__(16) float xs2[32 * HC];
    int tid = threadIdx.x;
    int row0 = blockIdx.x * 32;
    int nrows = NN - row0; if (nrows > 32) nrows = 32;

    for (int i = tid; i < 32 * (HC / 4); i += 128) {
        int r = i >> 4;               // 16 float4 per row
        int k4 = (i & 15) << 2;
        if (r < nrows) {
            float4 v = *(const float4*)(g_hid + (size_t)(row0 + r) * HC + k4);
            float* b = xs2 + (r >> 1) * (2 * HC) + (r & 1);
            b[2 * k4 + 0] = v.x; b[2 * k4 + 2] = v.y;
            b[2 * k4 + 4] = v.z; b[2 * k4 + 6] = v.w;
        }
    }
    __syncthreads();

    int warp = tid >> 5, lane = tid & 31;
    int c = lane << 1;                 // 2 consecutive output channels
    ull acc[4][2];
#pragma unroll
    for (int q = 0; q < 4; q++) { acc[q][0] = 0ull; acc[q][1] = 0ull; }

    const float* xb = xs2 + (warp * 4) * (2 * HC);
#pragma unroll 8
    for (int k = 0; k < HC; k++) {
        float2 w = *(const float2*)(g_Wlt + (k << 6) + c);
        ull w0 = pack2(w.x, w.x), w1 = pack2(w.y, w.y);
#pragma unroll
        for (int q = 0; q < 4; q++) {
            ull xp = *(const ull*)(xb + q * (2 * HC) + 2 * k);
            ffma2(acc[q][0], xp, w0);
            ffma2(acc[q][1], xp, w1);
        }
    }

    float b0 = blin[c], b1 = blin[c + 1];
#pragma unroll
    for (int q = 0; q < 4; q++) {
        int re = row0 + warp * 8 + q * 2;
        if (re >= NN) break;
        float lo0, hi0, lo1, hi1;
        unpack2(acc[q][0], lo0, hi0);
        unpack2(acc[q][1], lo1, hi1);
        *(float2*)(out + (size_t)re * OC + c) = make_float2(lo0 + b0, lo1 + b1);
        if (re + 1 < NN)
            *(float2*)(out + (size_t)(re + 1) * OC + c) = make_float2(hi0 + b0, hi1 + b1);
    }
}

// ---------------- launch ----------------
extern "C" void kernel_launch(void* const* d_in, const int* in_sizes, int n_in,
                              void* d_out, int out_size) {
    const float* x     = (const float*)d_in[0];
    const void*  ei    = d_in[1];
    const float* Wl    = (const float*)d_in[3];
    const float* Wr    = (const float*)d_in[4];
    const float* att   = (const float*)d_in[5];
    const float* bconv = (const float*)d_in[6];
    const float* Wlin  = (const float*)d_in[7];
    const float* blin  = (const float*)d_in[8];
    float* out = (float*)d_out;

    k_pre<<<196, 256>>>(Wl, Wr, Wlin, (const int*)ei);
    k_gh<<<GB + HB, 128>>>(x, ei);
    k_ss<<<SB + SCTB, 256>>>();
    k_aggr<<<296, 512>>>(att, bconv);
    k_out<<<(NN + 31) / 32, 128>>>(blin, out);
}

// round 14
// speedup vs baseline: 1.0031x; 1.0031x over previous
#include <cuda_runtime.h>
#include <cstdint>

#define NN 50000
#define NE 1200000
#define INC 128
#define HC 64
#define OC 64
#define SB 196                     // scan blocks (196*256 = 50176 >= NN)
#define GB 1563                    // gemm blocks ((NN+31)/32)
#define HB ((NE + 511) / 512)      // hist blocks (4 edges/thread, 128 thr)
#define SCTB ((NE + 1023) / 1024)  // scatter blocks (4 edges/thread, 256 thr)
#define AGB 296                    // aggr persistent blocks (2/SM)
#define NWARPS (AGB * 16)
#define NTILES ((NN + 127) / 128)  // out-phase tiles

#define NEG_INF __int_as_float(0xff800000)

typedef unsigned long long ull;

// ---------------- scratch ----------------
__device__ __align__(16) float g_xl[(size_t)NN * HC];
__device__ __align__(16) float g_xr[(size_t)NN * HC];
__device__ __align__(16) float g_hid[(size_t)NN * HC];
__device__ __align__(16) float g_Wt[INC * 128];
__device__ __align__(16) float g_Wlt[HC * OC];
__device__ int   g_cnt[SB * 256];      // degree counts; zeroed by scan for next replay
__device__ int   g_off[NN + 1];
__device__ int   g_srcs[NE];
__device__ __align__(16) ull g_dr[NE]; // packed (dst<<16|src)<<32 | rank
__device__ int   g_flag[SB];           // lookback: 0=invalid 1=agg 2=inclusive
__device__ int   g_agg[SB];
__device__ int   g_incl[SB];
__device__ int   g_scan_done;
__device__ int   g_work;               // aggr work-stealing node counter
__device__ int   g_work2;              // out-phase tile counter
__device__ int   g_done;               // finished aggr warps
__device__ int   g_probe;              // 1 => int32 storage, 0 => int64

// ---------------- helpers ----------------
__device__ __forceinline__ ull pack2(float lo, float hi) {
    ull r; asm("mov.b64 %0, {%1, %2};" : "=l"(r) : "f"(lo), "f"(hi)); return r;
}
__device__ __forceinline__ void unpack2(ull v, float& lo, float& hi) {
    asm("mov.b64 {%0, %1}, %2;" : "=f"(lo), "=f"(hi) : "l"(v));
}
__device__ __forceinline__ void ffma2(ull& d, ull a, ull b) {
    asm("fma.rn.f32x2 %0, %1, %2, %0;" : "+l"(d) : "l"(a), "l"(b));
}
__device__ __forceinline__ ull add2(ull a, ull b) {
    ull r; asm("add.rn.f32x2 %0, %1, %2;" : "=l"(r) : "l"(a), "l"(b)); return r;
}
__device__ __forceinline__ int load_idx(const void* ei, int pos, int is64) {
    int v = is64 ? (int)((const long long*)ei)[pos] : ((const int*)ei)[pos];
    return (v < 0) ? 0 : (v >= NN ? NN - 1 : v);
}

// ---------------- K0: weight transpose + dtype probe + control resets ----------------
__global__ void k_pre(const float* __restrict__ Wl, const float* __restrict__ Wr,
                      const float* __restrict__ Wlin, const int* __restrict__ ei32) {
    int t0 = blockIdx.x * blockDim.x + threadIdx.x;
    if (t0 < 32) {
        int v = 0;
#pragma unroll 8
        for (int it = 0; it < 32; it++) v |= ei32[2 * (t0 + 32 * it) + 1];
#pragma unroll
        for (int o = 16; o; o >>= 1) v |= __shfl_xor_sync(0xffffffffu, v, o);
        if (t0 == 0) {
            g_probe = (v != 0) ? 1 : 0;
            g_scan_done = 0; g_work = 0; g_work2 = 0; g_done = 0;
        }
    }
    if (t0 < SB) g_flag[t0] = 0;
    if (t0 < INC * 128) {
        int k = t0 >> 7, ch = t0 & 127;
        g_Wt[t0] = (ch < HC) ? Wl[ch * INC + k] : Wr[(ch - HC) * INC + k];
    }
    if (t0 < HC * OC) {
        int k = t0 >> 6, o = t0 & 63;
        g_Wlt[t0] = Wlin[o * HC + k];
    }
}

// ---------------- K1: MERGED projection GEMM + histogram/pack ----------------
__global__ void __launch_bounds__(128) k_gh(const float* __restrict__ x,
                                            const void* __restrict__ ei) {
    __shared__ __align__(16) float xs2[32 * INC];
    int tid = threadIdx.x;

    if (blockIdx.x >= GB) {
        int is64 = (g_probe == 0);
        int e0 = (blockIdx.x - GB) * 512 + tid;
#pragma unroll
        for (int k = 0; k < 4; k++) {
            int e = e0 + k * 128;
            if (e < NE) {
                int d = load_idx(ei, NE + e, is64);
                int s = load_idx(ei, e, is64);
                int r = atomicAdd(&g_cnt[d], 1);
                g_dr[e] = ((ull)(((unsigned)d << 16) | (unsigned)s) << 32) | (unsigned)r;
            }
        }
        return;
    }

    int row0 = blockIdx.x * 32;
    int nrows = NN - row0; if (nrows > 32) nrows = 32;

    for (int i = tid; i < 32 * (INC / 4); i += 128) {
        int r = i >> 5;
        int k4 = (i & 31) << 2;
        if (r < nrows) {
            float4 v = *(const float4*)(x + (size_t)(row0 + r) * INC + k4);
            float* b = xs2 + (r >> 1) * (2 * INC) + (r & 1);
            b[2 * k4 + 0] = v.x; b[2 * k4 + 2] = v.y;
            b[2 * k4 + 4] = v.z; b[2 * k4 + 6] = v.w;
        }
    }
    __syncthreads();

    int warp = tid >> 5, lane = tid & 31;
    int c = lane << 2;
    ull acc[4][4];
#pragma unroll
    for (int q = 0; q < 4; q++)
#pragma unroll
        for (int j = 0; j < 4; j++) acc[q][j] = 0ull;

    const float* xb = xs2 + (warp * 4) * (2 * INC);
#pragma unroll 8
    for (int k = 0; k < INC; k++) {
        float4 w = *(const float4*)(g_Wt + (k << 7) + c);
        ull w0 = pack2(w.x, w.x), w1 = pack2(w.y, w.y);
        ull w2 = pack2(w.z, w.z), w3 = pack2(w.w, w.w);
#pragma unroll
        for (int q = 0; q < 4; q++) {
            ull xp = *(const ull*)(xb + q * (2 * INC) + 2 * k);
            ffma2(acc[q][0], xp, w0);
            ffma2(acc[q][1], xp, w1);
            ffma2(acc[q][2], xp, w2);
            ffma2(acc[q][3], xp, w3);
        }
    }

    float* base = (c < HC) ? (g_xl + c) : (g_xr + (c - HC));
#pragma unroll
    for (int q = 0; q < 4; q++) {
        int re = row0 + warp * 8 + q * 2;
        if (re >= NN) break;
        float lo0, hi0, lo1, hi1, lo2, hi2, lo3, hi3;
        unpack2(acc[q][0], lo0, hi0); unpack2(acc[q][1], lo1, hi1);
        unpack2(acc[q][2], lo2, hi2); unpack2(acc[q][3], lo3, hi3);
        *(float4*)(base + (size_t)re * HC) = make_float4(lo0, lo1, lo2, lo3);
        if (re + 1 < NN)
            *(float4*)(base + (size_t)(re + 1) * HC) = make_float4(hi0, hi1, hi2, hi3);
    }
}

// ---------------- K2: MERGED decoupled-lookback scan + scatter ----------------
__global__ void __launch_bounds__(256) k_ss() {
    int tid = threadIdx.x;
    int b = blockIdx.x;

    if (b < SB) {
        __shared__ int wsum[8];
        __shared__ int s_base;
        int i = b * 256 + tid;
        int v = g_cnt[i];
        g_cnt[i] = 0;
        int lane = tid & 31, wid = tid >> 5;
        int xv = v;
#pragma unroll
        for (int o = 1; o < 32; o <<= 1) {
            int y = __shfl_up_sync(0xffffffffu, xv, o);
            if (lane >= o) xv += y;
        }
        if (lane == 31) wsum[wid] = xv;
        __syncthreads();
        if (tid < 8) {
            int w = wsum[tid];
#pragma unroll
            for (int o = 1; o < 8; o <<= 1) {
                int y = __shfl_up_sync(0x000000ffu, w, o);
                if (tid >= o) w += y;
            }
            wsum[tid] = w;
        }
        __syncthreads();
        int excl = xv - v + ((wid > 0) ? wsum[wid - 1] : 0);
        int T = wsum[7];

        if (b == 0) {
            if (tid == 0) {
                g_incl[0] = T;
                __threadfence();
                atomicExch(&g_flag[0], 2);
                s_base = 0;
            }
        } else if (tid < 32) {
            if (tid == 0) {
                g_agg[b] = T;
                __threadfence();
                atomicExch(&g_flag[b], 1);
            }
            __syncwarp();
            int sum = 0;
            int p = b - 1;
            for (;;) {
                int idx = p - tid;
                int f = 0;
                if (idx >= 0) {
                    do { f = atomicAdd(&g_flag[idx], 0); } while (f == 0);
                }
                unsigned m2 = __ballot_sync(0xffffffffu, (idx >= 0) && (f == 2));
                int kcut = m2 ? (__ffs(m2) - 1) : 32;
                __threadfence();
                int contrib = 0;
                if (idx >= 0 && tid <= kcut)
                    contrib = (tid == kcut) ? atomicAdd(&g_incl[idx], 0)
                                            : atomicAdd(&g_agg[idx], 0);
#pragma unroll
                for (int o = 16; o; o >>= 1) contrib += __shfl_xor_sync(0xffffffffu, contrib, o);
                sum += contrib;
                if (m2) break;
                p -= 32;
            }
            if (tid == 0) {
                g_incl[b] = sum + T;
                __threadfence();
                atomicExch(&g_flag[b], 2);
                s_base = sum;
            }
        }
        __syncthreads();
        if (i < NN) g_off[i] = excl + s_base;
        if (b == 0 && tid == 0) g_off[NN] = NE;
        __threadfence();
        __syncthreads();
        if (tid == 0) atomicAdd(&g_scan_done, 1);
        return;
    }

    if (tid == 0) {
        while (atomicAdd(&g_scan_done, 0) < SB) __nanosleep(64);
    }
    __syncthreads();
    __threadfence();

    int e0 = (b - SB) * 1024 + tid;
#pragma unroll
    for (int k = 0; k < 4; k++) {
        int e = e0 + k * 256;
        if (e < NE) {
            ull dr = g_dr[e];
            unsigned hi = (unsigned)(dr >> 32);
            int d = hi >> 16;
            int s = hi & 0xFFFF;
            int r = (int)(unsigned)dr;
            g_srcs[g_off[d] + r] = s;
        }
    }
}

// ---------------- K3: persistent aggregation -> g_hid, then block-tiled out GEMM ----------------
// Phase A: warp-level work stealing over nodes (unchanged math from R13's measured-good aggr).
// Phase B: after ALL warps chip-wide finish (g_done spin; all AGB blocks co-resident),
//          blocks steal 128-row tiles and run the dense 64x64 GEMM (weights amortized over rows).
__global__ void __launch_bounds__(512, 2) k_aggr(const float* __restrict__ att,
                                                 const float* __restrict__ bias,
                                                 const float* __restrict__ blin,
                                                 float* __restrict__ out) {
    __shared__ __align__(16) float xs2[64 * 2 * HC];   // 32 KB (out-phase staging)
    __shared__ int s_tile;
    int tid = threadIdx.x;
    int lane = tid & 31;
    int quarter = lane >> 3, l8 = lane & 7;
    int c0 = l8 * 4, c1 = 32 + l8 * 4;

    {
        // packed 0.6*att pairs, scalar 0.4*att
        float4 at0 = *(const float4*)(att + c0);
        float4 at1 = *(const float4*)(att + c1);
        ull a6p00 = pack2(0.6f * at0.x, 0.6f * at0.y);
        ull a6p01 = pack2(0.6f * at0.z, 0.6f * at0.w);
        ull a6p10 = pack2(0.6f * at1.x, 0.6f * at1.y);
        ull a6p11 = pack2(0.6f * at1.z, 0.6f * at1.w);
        float a40x = 0.4f * at0.x, a40y = 0.4f * at0.y, a40z = 0.4f * at0.z, a40w = 0.4f * at0.w;
        float a41x = 0.4f * at1.x, a41y = 0.4f * at1.y, a41z = 0.4f * at1.z, a41w = 0.4f * at1.w;

        for (;;) {
            int n;
            if (lane == 0) n = atomicAdd(&g_work, 1);
            n = __shfl_sync(0xffffffffu, n, 0);
            if (n >= NN) break;

            const float* xri = g_xr + ((unsigned)n << 6);
            ulonglong2 xrp0 = *(const ulonglong2*)(xri + c0);
            ulonglong2 xrp1 = *(const ulonglong2*)(xri + c1);

            ull kp = 0ull;
            ffma2(kp, xrp0.x, a6p00); ffma2(kp, xrp0.y, a6p01);
            ffma2(kp, xrp1.x, a6p10); ffma2(kp, xrp1.y, a6p11);
            float klo, khi; unpack2(kp, klo, khi);
            float K = klo + khi;

            ull accp[4] = {0ull, 0ull, 0ull, 0ull};
            float d;

            // self loop (all quarters, 0.25 scale; merge tree sums exactly to 1x)
            const float* xli = g_xl + ((unsigned)n << 6);
            ulonglong2 v0p = *(const ulonglong2*)(xli + c0);
            ulonglong2 v1p = *(const ulonglong2*)(xli + c1);
            {
                ull sp = 0ull;
                ffma2(sp, v0p.x, a6p00); ffma2(sp, v0p.y, a6p01);
                ffma2(sp, v1p.x, a6p10); ffma2(sp, v1p.y, a6p11);
                ull u0 = add2(v0p.x, xrp0.x), u1 = add2(v0p.y, xrp0.y);
                ull u2 = add2(v1p.x, xrp1.x), u3 = add2(v1p.y, xrp1.y);
                float ul, uh, sa = K;
                unpack2(u0, ul, uh); sa = fmaf(fabsf(ul), a40x, sa); sa = fmaf(fabsf(uh), a40y, sa);
                unpack2(u1, ul, uh); sa = fmaf(fabsf(ul), a40z, sa); sa = fmaf(fabsf(uh), a40w, sa);
                unpack2(u2, ul, uh); sa = fmaf(fabsf(ul), a41x, sa); sa = fmaf(fabsf(uh), a41y, sa);
                unpack2(u3, ul, uh); sa = fmaf(fabsf(ul), a41z, sa); sa = fmaf(fabsf(uh), a41w, sa);
                float slo, shi; unpack2(sp, slo, shi);
                float s = sa + slo + shi;
                s += __shfl_xor_sync(0xffffffffu, s, 1);
                s += __shfl_xor_sync(0xffffffffu, s, 2);
                s += __shfl_xor_sync(0xffffffffu, s, 4);
                float pe = 0.25f * __expf(s);
                d = pe;
                ull pep = pack2(pe, pe);
                ffma2(accp[0], pep, v0p.x); ffma2(accp[1], pep, v0p.y);
                ffma2(accp[2], pep, v1p.x); ffma2(accp[3], pep, v1p.y);
            }

            // edges: 4 in flight (one per quarter), src prefetch
            int off = g_off[n], end = g_off[n + 1];
            int my = off + quarter;
            bool vcur = (my < end);
            int jcur = vcur ? g_srcs[my] : n;
            for (int e = off; e < end; e += 4) {
                int myn = my + 4;
                bool vn = (myn < end);
                int jn = vn ? g_srcs[myn] : n;

                const float* vp = g_xl + ((unsigned)jcur << 6);
                v0p = *(const ulonglong2*)(vp + c0);
                v1p = *(const ulonglong2*)(vp + c1);
                ull sp = 0ull;
                ffma2(sp, v0p.x, a6p00); ffma2(sp, v0p.y, a6p01);
                ffma2(sp, v1p.x, a6p10); ffma2(sp, v1p.y, a6p11);
                ull u0 = add2(v0p.x, xrp0.x), u1 = add2(v0p.y, xrp0.y);
                ull u2 = add2(v1p.x, xrp1.x), u3 = add2(v1p.y, xrp1.y);
                float ul, uh, sa = K;
                unpack2(u0, ul, uh); sa = fmaf(fabsf(ul), a40x, sa); sa = fmaf(fabsf(uh), a40y, sa);
                unpack2(u1, ul, uh); sa = fmaf(fabsf(ul), a40z, sa); sa = fmaf(fabsf(uh), a40w, sa);
                unpack2(u2, ul, uh); sa = fmaf(fabsf(ul), a41x, sa); sa = fmaf(fabsf(uh), a41y, sa);
                unpack2(u3, ul, uh); sa = fmaf(fabsf(ul), a41z, sa); sa = fmaf(fabsf(uh), a41w, sa);
                float slo, shi; unpack2(sp, slo, shi);
                float s = sa + slo + shi;
                float q = vcur ? s : NEG_INF;
                q += __shfl_xor_sync(0xffffffffu, q, 1);
                q += __shfl_xor_sync(0xffffffffu, q, 2);
                q += __shfl_xor_sync(0xffffffffu, q, 4);
                float pe = __expf(q);
                d += pe;
                ull pep = pack2(pe, pe);
                ffma2(accp[0], pep, v0p.x); ffma2(accp[1], pep, v0p.y);
                ffma2(accp[2], pep, v1p.x); ffma2(accp[3], pep, v1p.y);

                my = myn; vcur = vn; jcur = jn;
            }

            float acc[8];
            unpack2(accp[0], acc[0], acc[1]); unpack2(accp[1], acc[2], acc[3]);
            unpack2(accp[2], acc[4], acc[5]); unpack2(accp[3], acc[6], acc[7]);
            d += __shfl_xor_sync(0xffffffffu, d, 8);
            d += __shfl_xor_sync(0xffffffffu, d, 16);
#pragma unroll
            for (int k = 0; k < 8; k++) acc[k] += __shfl_xor_sync(0xffffffffu, acc[k], 8);
#pragma unroll
            for (int k = 0; k < 8; k++) acc[k] += __shfl_xor_sync(0xffffffffu, acc[k], 16);

            float inv = 1.0f / (d + 1e-16f);
            float4 b0 = *(const float4*)(bias + c0);
            float4 b1 = *(const float4*)(bias + c1);
            float h[8];
            h[0] = acc[0] * inv + b0.x; h[1] = acc[1] * inv + b0.y;
            h[2] = acc[2] * inv + b0.z; h[3] = acc[3] * inv + b0.w;
            h[4] = acc[4] * inv + b1.x; h[5] = acc[5] * inv + b1.y;
            h[6] = acc[6] * inv + b1.z; h[7] = acc[7] * inv + b1.w;
#pragma unroll
            for (int k = 0; k < 8; k++) h[k] = (h[k] > 0.0f) ? h[k] : expm1f(h[k]);

            if (quarter == 0) {
                float* hp = g_hid + ((size_t)n << 6);
                *(float4*)(hp + c0) = make_float4(h[0], h[1], h[2], h[3]);
                *(float4*)(hp + c1) = make_float4(h[4], h[5], h[6], h[7]);
            }
        }
    }

    // ---- phase B barrier: wait for ALL aggr warps chip-wide ----
    __threadfence();
    if (lane == 0) atomicAdd(&g_done, 1);
    __syncthreads();
    if (tid == 0) {
        while (atomicAdd(&g_done, 0) < NWARPS) __nanosleep(64);
    }
    __syncthreads();
    __threadfence();

    // ---- phase B: dense 64x64 out GEMM, 128-row tiles, block-cooperative ----
    int warp = tid >> 5;
    for (;;) {
        if (tid == 0) s_tile = atomicAdd(&g_work2, 1);
        __syncthreads();
        int t = s_tile;
        __syncthreads();
        if (t >= NTILES) break;
        int row0 = t * 128;
        int nrows = NN - row0; if (nrows > 128) nrows = 128;

        for (int i = tid; i < 128 * (HC / 4); i += 512) {
            int r = i >> 4;                // 16 float4 per row
            int k4 = (i & 15) << 2;
            if (r < nrows) {
                float4 v = *(const float4*)(g_hid + (size_t)(row0 + r) * HC + k4);
                float* b = xs2 + (r >> 1) * (2 * HC) + (r & 1);
                b[2 * k4 + 0] = v.x; b[2 * k4 + 2] = v.y;
                b[2 * k4 + 4] = v.z; b[2 * k4 + 6] = v.w;
            }
        }
        __syncthreads();

        int c = lane << 1;
        ull acc[4][2];
#pragma unroll
        for (int q = 0; q < 4; q++) { acc[q][0] = 0ull; acc[q][1] = 0ull; }

        const float* xb = xs2 + (warp * 4) * (2 * HC);
#pragma unroll 8
        for (int k = 0; k < HC; k++) {
            float2 w = *(const float2*)(g_Wlt + (k << 6) + c);
            ull w0 = pack2(w.x, w.x), w1 = pack2(w.y, w.y);
#pragma unroll
            for (int q = 0; q < 4; q++) {
                ull xp = *(const ull*)(xb + q * (2 * HC) + 2 * k);
                ffma2(acc[q][0], xp, w0);
                ffma2(acc[q][1], xp, w1);
            }
        }

        float b0 = blin[c], b1 = blin[c + 1];
#pragma unroll
        for (int q = 0; q < 4; q++) {
            int re = row0 + warp * 8 + q * 2;
            if (re >= NN) break;
            float lo0, hi0, lo1, hi1;
            unpack2(acc[q][0], lo0, hi0);
            unpack2(acc[q][1], lo1, hi1);
            *(float2*)(out + (size_t)re * OC + c) = make_float2(lo0 + b0, lo1 + b1);
            if (re + 1 < NN)
                *(float2*)(out + (size_t)(re + 1) * OC + c) = make_float2(hi0 + b0, hi1 + b1);
        }
        __syncthreads();
    }
}

// ---------------- launch ----------------
extern "C" void kernel_launch(void* const* d_in, const int* in_sizes, int n_in,
                              void* d_out, int out_size) {
    const float* x     = (const float*)d_in[0];
    const void*  ei    = d_in[1];
    const float* Wl    = (const float*)d_in[3];
    const float* Wr    = (const float*)d_in[4];
    const float* att   = (const float*)d_in[5];
    const float* bconv = (const float*)d_in[6];
    const float* Wlin  = (const float*)d_in[7];
    const float* blin  = (const float*)d_in[8];
    float* out = (float*)d_out;

    k_pre<<<196, 256>>>(Wl, Wr, Wlin, (const int*)ei);
    k_gh<<<GB + HB, 128>>>(x, ei);
    k_ss<<<SB + SCTB, 256>>>();
    k_aggr<<<AGB, 512>>>(att, bconv, blin, out);
}

// round 15
// speedup vs baseline: 1.0446x; 1.0414x over previous
#include <cuda_runtime.h>
#include <cstdint>

#define NN 50000
#define NE 1200000
#define INC 128
#define HC 64
#define OC 64
#define SB 196                     // scan blocks (196*256 = 50176 >= NN)
#define GB 1563                    // gemm blocks ((NN+31)/32)
#define HB ((NE + 511) / 512)      // hist blocks (4 edges/thread, 128 thr)
#define SCTB ((NE + 1023) / 1024)  // scatter blocks (4 edges/thread, 256 thr)

#define NEG_INF __int_as_float(0xff800000)

typedef unsigned long long ull;

// ---------------- scratch ----------------
__device__ __align__(16) float g_xl[(size_t)NN * HC];
__device__ __align__(16) float g_xr[(size_t)NN * HC];
__device__ __align__(16) float g_Wt[INC * 128];
__device__ __align__(16) float g_Wlt[HC * OC];
__device__ int   g_cnt[SB * 256];      // degree counts; zeroed by scan for next replay
__device__ int   g_off[NN + 1];
__device__ int   g_srcs[NE];
__device__ __align__(16) ull g_dr[NE]; // packed (dst<<16|src)<<32 | rank
__device__ int   g_flag[SB];           // lookback: 0=invalid 1=agg 2=inclusive
__device__ int   g_agg[SB];
__device__ int   g_incl[SB];
__device__ int   g_scan_done;
__device__ int   g_work;               // work-stealing node counter (steps of 2)
__device__ int   g_probe;              // 1 => int32 storage, 0 => int64

// ---------------- helpers ----------------
__device__ __forceinline__ ull pack2(float lo, float hi) {
    ull r; asm("mov.b64 %0, {%1, %2};" : "=l"(r) : "f"(lo), "f"(hi)); return r;
}
__device__ __forceinline__ void unpack2(ull v, float& lo, float& hi) {
    asm("mov.b64 {%0, %1}, %2;" : "=f"(lo), "=f"(hi) : "l"(v));
}
__device__ __forceinline__ void ffma2(ull& d, ull a, ull b) {
    asm("fma.rn.f32x2 %0, %1, %2, %0;" : "+l"(d) : "l"(a), "l"(b));
}
__device__ __forceinline__ ull add2(ull a, ull b) {
    ull r; asm("add.rn.f32x2 %0, %1, %2;" : "=l"(r) : "l"(a), "l"(b)); return r;
}
__device__ __forceinline__ int load_idx(const void* ei, int pos, int is64) {
    int v = is64 ? (int)((const long long*)ei)[pos] : ((const int*)ei)[pos];
    return (v < 0) ? 0 : (v >= NN ? NN - 1 : v);
}

// ---------------- K0: weight transpose + dtype probe + control resets ----------------
__global__ void k_pre(const float* __restrict__ Wl, const float* __restrict__ Wr,
                      const float* __restrict__ Wlin, const int* __restrict__ ei32) {
    int t0 = blockIdx.x * blockDim.x + threadIdx.x;
    if (t0 < 32) {
        int v = 0;
#pragma unroll 8
        for (int it = 0; it < 32; it++) v |= ei32[2 * (t0 + 32 * it) + 1];
#pragma unroll
        for (int o = 16; o; o >>= 1) v |= __shfl_xor_sync(0xffffffffu, v, o);
        if (t0 == 0) { g_probe = (v != 0) ? 1 : 0; g_scan_done = 0; g_work = 0; }
    }
    if (t0 < SB) g_flag[t0] = 0;
    if (t0 < INC * 128) {
        int k = t0 >> 7, ch = t0 & 127;
        g_Wt[t0] = (ch < HC) ? Wl[ch * INC + k] : Wr[(ch - HC) * INC + k];
    }
    if (t0 < HC * OC) {
        int k = t0 >> 6, o = t0 & 63;
        g_Wlt[t0] = Wlin[o * HC + k];
    }
}

// ---------------- K1: MERGED projection GEMM + histogram/pack (4 edges/thread) ----------------
__global__ void __launch_bounds__(128) k_gh(const float* __restrict__ x,
                                            const void* __restrict__ ei) {
    __shared__ __align__(16) float xs2[32 * INC];
    int tid = threadIdx.x;

    if (blockIdx.x >= GB) {
        int is64 = (g_probe == 0);
        int e0 = (blockIdx.x - GB) * 512 + tid;
#pragma unroll
        for (int k = 0; k < 4; k++) {
            int e = e0 + k * 128;
            if (e < NE) {
                int d = load_idx(ei, NE + e, is64);
                int s = load_idx(ei, e, is64);
                int r = atomicAdd(&g_cnt[d], 1);
                g_dr[e] = ((ull)(((unsigned)d << 16) | (unsigned)s) << 32) | (unsigned)r;
            }
        }
        return;
    }

    int row0 = blockIdx.x * 32;
    int nrows = NN - row0; if (nrows > 32) nrows = 32;

    for (int i = tid; i < 32 * (INC / 4); i += 128) {
        int r = i >> 5;
        int k4 = (i & 31) << 2;
        if (r < nrows) {
            float4 v = *(const float4*)(x + (size_t)(row0 + r) * INC + k4);
            float* b = xs2 + (r >> 1) * (2 * INC) + (r & 1);
            b[2 * k4 + 0] = v.x; b[2 * k4 + 2] = v.y;
            b[2 * k4 + 4] = v.z; b[2 * k4 + 6] = v.w;
        }
    }
    __syncthreads();

    int warp = tid >> 5, lane = tid & 31;
    int c = lane << 2;
    ull acc[4][4];
#pragma unroll
    for (int q = 0; q < 4; q++)
#pragma unroll
        for (int j = 0; j < 4; j++) acc[q][j] = 0ull;

    const float* xb = xs2 + (warp * 4) * (2 * INC);
#pragma unroll 8
    for (int k = 0; k < INC; k++) {
        float4 w = *(const float4*)(g_Wt + (k << 7) + c);
        ull w0 = pack2(w.x, w.x), w1 = pack2(w.y, w.y);
        ull w2 = pack2(w.z, w.z), w3 = pack2(w.w, w.w);
#pragma unroll
        for (int q = 0; q < 4; q++) {
            ull xp = *(const ull*)(xb + q * (2 * INC) + 2 * k);
            ffma2(acc[q][0], xp, w0);
            ffma2(acc[q][1], xp, w1);
            ffma2(acc[q][2], xp, w2);
            ffma2(acc[q][3], xp, w3);
        }
    }

    float* base = (c < HC) ? (g_xl + c) : (g_xr + (c - HC));
#pragma unroll
    for (int q = 0; q < 4; q++) {
        int re = row0 + warp * 8 + q * 2;
        if (re >= NN) break;
        float lo0, hi0, lo1, hi1, lo2, hi2, lo3, hi3;
        unpack2(acc[q][0], lo0, hi0); unpack2(acc[q][1], lo1, hi1);
        unpack2(acc[q][2], lo2, hi2); unpack2(acc[q][3], lo3, hi3);
        *(float4*)(base + (size_t)re * HC) = make_float4(lo0, lo1, lo2, lo3);
        if (re + 1 < NN)
            *(float4*)(base + (size_t)(re + 1) * HC) = make_float4(hi0, hi1, hi2, hi3);
    }
}

// ---------------- K2: MERGED decoupled-lookback scan + scatter ----------------
__global__ void __launch_bounds__(256) k_ss() {
    int tid = threadIdx.x;
    int b = blockIdx.x;

    if (b < SB) {
        __shared__ int wsum[8];
        __shared__ int s_base;
        int i = b * 256 + tid;
        int v = g_cnt[i];
        g_cnt[i] = 0;
        int lane = tid & 31, wid = tid >> 5;
        int xv = v;
#pragma unroll
        for (int o = 1; o < 32; o <<= 1) {
            int y = __shfl_up_sync(0xffffffffu, xv, o);
            if (lane >= o) xv += y;
        }
        if (lane == 31) wsum[wid] = xv;
        __syncthreads();
        if (tid < 8) {
            int w = wsum[tid];
#pragma unroll
            for (int o = 1; o < 8; o <<= 1) {
                int y = __shfl_up_sync(0x000000ffu, w, o);
                if (tid >= o) w += y;
            }
            wsum[tid] = w;
        }
        __syncthreads();
        int excl = xv - v + ((wid > 0) ? wsum[wid - 1] : 0);
        int T = wsum[7];

        if (b == 0) {
            if (tid == 0) {
                g_incl[0] = T;
                __threadfence();
                atomicExch(&g_flag[0], 2);
                s_base = 0;
            }
        } else if (tid < 32) {
            if (tid == 0) {
                g_agg[b] = T;
                __threadfence();
                atomicExch(&g_flag[b], 1);
            }
            __syncwarp();
            int sum = 0;
            int p = b - 1;
            for (;;) {
                int idx = p - tid;
                int f = 0;
                if (idx >= 0) {
                    do { f = atomicAdd(&g_flag[idx], 0); } while (f == 0);
                }
                unsigned m2 = __ballot_sync(0xffffffffu, (idx >= 0) && (f == 2));
                int kcut = m2 ? (__ffs(m2) - 1) : 32;
                __threadfence();
                int contrib = 0;
                if (idx >= 0 && tid <= kcut)
                    contrib = (tid == kcut) ? atomicAdd(&g_incl[idx], 0)
                                            : atomicAdd(&g_agg[idx], 0);
#pragma unroll
                for (int o = 16; o; o >>= 1) contrib += __shfl_xor_sync(0xffffffffu, contrib, o);
                sum += contrib;
                if (m2) break;
                p -= 32;
            }
            if (tid == 0) {
                g_incl[b] = sum + T;
                __threadfence();
                atomicExch(&g_flag[b], 2);
                s_base = sum;
            }
        }
        __syncthreads();
        if (i < NN) g_off[i] = excl + s_base;
        if (b == 0 && tid == 0) g_off[NN] = NE;
        __threadfence();
        __syncthreads();
        if (tid == 0) atomicAdd(&g_scan_done, 1);
        return;
    }

    if (tid == 0) {
        while (atomicAdd(&g_scan_done, 0) < SB) __nanosleep(64);
    }
    __syncthreads();
    __threadfence();

    int e0 = (b - SB) * 1024 + tid;
#pragma unroll
    for (int k = 0; k < 4; k++) {
        int e = e0 + k * 256;
        if (e < NE) {
            ull dr = g_dr[e];
            unsigned hi = (unsigned)(dr >> 32);
            int d = hi >> 16;
            int s = hi & 0xFFFF;
            int r = (int)(unsigned)dr;
            g_srcs[g_off[d] + r] = s;
        }
    }
}

// ---------------- K3: persistent aggregation, 2 nodes/warp + shared-weight epilogue ----------------
// Warp steals node PAIRS (NN even -> both always valid). Aggregation identical to the
// measured-good R12 loop. Epilogue GEMV done once per pair: every W_lin LDS is shared
// between both nodes (halves the dominant weight-load cost of the fused epilogue).
__global__ void __launch_bounds__(512, 2) k_aggr(const float* __restrict__ att,
                                                 const float* __restrict__ bias,
                                                 const float* __restrict__ blin,
                                                 float* __restrict__ out) {
    __shared__ __align__(16) float sW[HC * OC];   // 16 KB
    __shared__ __align__(16) float sh[32][HC];    // 8 KB (2 nodes per warp)
    int tid = threadIdx.x;
    for (int idx = tid; idx < HC * OC / 4; idx += 512)
        *(float4*)&sW[idx * 4] = *(const float4*)&g_Wlt[idx * 4];
    __syncthreads();

    int warp = tid >> 5, lane = tid & 31;
    int quarter = lane >> 3, l8 = lane & 7;
    int c0 = l8 * 4, c1 = 32 + l8 * 4;

    // packed 0.6*att pairs, scalar 0.4*att
    float4 at0 = *(const float4*)(att + c0);
    float4 at1 = *(const float4*)(att + c1);
    ull a6p00 = pack2(0.6f * at0.x, 0.6f * at0.y);
    ull a6p01 = pack2(0.6f * at0.z, 0.6f * at0.w);
    ull a6p10 = pack2(0.6f * at1.x, 0.6f * at1.y);
    ull a6p11 = pack2(0.6f * at1.z, 0.6f * at1.w);
    float a40x = 0.4f * at0.x, a40y = 0.4f * at0.y, a40z = 0.4f * at0.z, a40w = 0.4f * at0.w;
    float a41x = 0.4f * at1.x, a41y = 0.4f * at1.y, a41z = 0.4f * at1.z, a41w = 0.4f * at1.w;

    for (;;) {
        int n0;
        if (lane == 0) n0 = atomicAdd(&g_work, 2);
        n0 = __shfl_sync(0xffffffffu, n0, 0);
        if (n0 >= NN) break;

#pragma unroll 1
        for (int sub = 0; sub < 2; sub++) {
            int n = n0 + sub;                     // NN even => n < NN always

            const float* xri = g_xr + ((unsigned)n << 6);
            ulonglong2 xrp0 = *(const ulonglong2*)(xri + c0);
            ulonglong2 xrp1 = *(const ulonglong2*)(xri + c1);

            ull kp = 0ull;
            ffma2(kp, xrp0.x, a6p00); ffma2(kp, xrp0.y, a6p01);
            ffma2(kp, xrp1.x, a6p10); ffma2(kp, xrp1.y, a6p11);
            float klo, khi; unpack2(kp, klo, khi);
            float K = klo + khi;

            ull accp[4] = {0ull, 0ull, 0ull, 0ull};
            float d;

            // self loop (all quarters, 0.25 scale; merge tree sums exactly to 1x)
            const float* xli = g_xl + ((unsigned)n << 6);
            ulonglong2 v0p = *(const ulonglong2*)(xli + c0);
            ulonglong2 v1p = *(const ulonglong2*)(xli + c1);
            {
                ull sp = 0ull;
                ffma2(sp, v0p.x, a6p00); ffma2(sp, v0p.y, a6p01);
                ffma2(sp, v1p.x, a6p10); ffma2(sp, v1p.y, a6p11);
                ull u0 = add2(v0p.x, xrp0.x), u1 = add2(v0p.y, xrp0.y);
                ull u2 = add2(v1p.x, xrp1.x), u3 = add2(v1p.y, xrp1.y);
                float ul, uh, sa = K;
                unpack2(u0, ul, uh); sa = fmaf(fabsf(ul), a40x, sa); sa = fmaf(fabsf(uh), a40y, sa);
                unpack2(u1, ul, uh); sa = fmaf(fabsf(ul), a40z, sa); sa = fmaf(fabsf(uh), a40w, sa);
                unpack2(u2, ul, uh); sa = fmaf(fabsf(ul), a41x, sa); sa = fmaf(fabsf(uh), a41y, sa);
                unpack2(u3, ul, uh); sa = fmaf(fabsf(ul), a41z, sa); sa = fmaf(fabsf(uh), a41w, sa);
                float slo, shi; unpack2(sp, slo, shi);
                float s = sa + slo + shi;
                s += __shfl_xor_sync(0xffffffffu, s, 1);
                s += __shfl_xor_sync(0xffffffffu, s, 2);
                s += __shfl_xor_sync(0xffffffffu, s, 4);
                float pe = 0.25f * __expf(s);
                d = pe;
                ull pep = pack2(pe, pe);
                ffma2(accp[0], pep, v0p.x); ffma2(accp[1], pep, v0p.y);
                ffma2(accp[2], pep, v1p.x); ffma2(accp[3], pep, v1p.y);
            }

            // edges: 4 in flight (one per quarter), src prefetch
            int off = g_off[n], end = g_off[n + 1];
            int my = off + quarter;
            bool vcur = (my < end);
            int jcur = vcur ? g_srcs[my] : n;
            for (int e = off; e < end; e += 4) {
                int myn = my + 4;
                bool vn = (myn < end);
                int jn = vn ? g_srcs[myn] : n;

                const float* vp = g_xl + ((unsigned)jcur << 6);
                v0p = *(const ulonglong2*)(vp + c0);
                v1p = *(const ulonglong2*)(vp + c1);
                ull sp = 0ull;
                ffma2(sp, v0p.x, a6p00); ffma2(sp, v0p.y, a6p01);
                ffma2(sp, v1p.x, a6p10); ffma2(sp, v1p.y, a6p11);
                ull u0 = add2(v0p.x, xrp0.x), u1 = add2(v0p.y, xrp0.y);
                ull u2 = add2(v1p.x, xrp1.x), u3 = add2(v1p.y, xrp1.y);
                float ul, uh, sa = K;
                unpack2(u0, ul, uh); sa = fmaf(fabsf(ul), a40x, sa); sa = fmaf(fabsf(uh), a40y, sa);
                unpack2(u1, ul, uh); sa = fmaf(fabsf(ul), a40z, sa); sa = fmaf(fabsf(uh), a40w, sa);
                unpack2(u2, ul, uh); sa = fmaf(fabsf(ul), a41x, sa); sa = fmaf(fabsf(uh), a41y, sa);
                unpack2(u3, ul, uh); sa = fmaf(fabsf(ul), a41z, sa); sa = fmaf(fabsf(uh), a41w, sa);
                float slo, shi; unpack2(sp, slo, shi);
                float s = sa + slo + shi;
                float q = vcur ? s : NEG_INF;
                q += __shfl_xor_sync(0xffffffffu, q, 1);
                q += __shfl_xor_sync(0xffffffffu, q, 2);
                q += __shfl_xor_sync(0xffffffffu, q, 4);
                float pe = __expf(q);             // 0 for invalid
                d += pe;
                ull pep = pack2(pe, pe);
                ffma2(accp[0], pep, v0p.x); ffma2(accp[1], pep, v0p.y);
                ffma2(accp[2], pep, v1p.x); ffma2(accp[3], pep, v1p.y);

                my = myn; vcur = vn; jcur = jn;
            }

            // unpack + merge quarters
            float acc[8];
            unpack2(accp[0], acc[0], acc[1]); unpack2(accp[1], acc[2], acc[3]);
            unpack2(accp[2], acc[4], acc[5]); unpack2(accp[3], acc[6], acc[7]);
            d += __shfl_xor_sync(0xffffffffu, d, 8);
            d += __shfl_xor_sync(0xffffffffu, d, 16);
#pragma unroll
            for (int k = 0; k < 8; k++) acc[k] += __shfl_xor_sync(0xffffffffu, acc[k], 8);
#pragma unroll
            for (int k = 0; k < 8; k++) acc[k] += __shfl_xor_sync(0xffffffffu, acc[k], 16);

            float inv = 1.0f / (d + 1e-16f);
            float4 b0 = *(const float4*)(bias + c0);
            float4 b1 = *(const float4*)(bias + c1);
            float h[8];
            h[0] = acc[0] * inv + b0.x; h[1] = acc[1] * inv + b0.y;
            h[2] = acc[2] * inv + b0.z; h[3] = acc[3] * inv + b0.w;
            h[4] = acc[4] * inv + b1.x; h[5] = acc[5] * inv + b1.y;
            h[6] = acc[6] * inv + b1.z; h[7] = acc[7] * inv + b1.w;
#pragma unroll
            for (int k = 0; k < 8; k++) h[k] = (h[k] > 0.0f) ? h[k] : expm1f(h[k]);

            if (quarter == 0) {
                float* hp = sh[warp * 2 + sub];
                *(float4*)(hp + c0) = make_float4(h[0], h[1], h[2], h[3]);
                *(float4*)(hp + c1) = make_float4(h[4], h[5], h[6], h[7]);
            }
        }
        __syncwarp();

        // ---- shared-weight epilogue for BOTH nodes: lane owns out channels c, c+1 ----
        int c = lane << 1;
        ull accA = 0ull, accB = 0ull;
        const float* hA = sh[warp * 2 + 0];
        const float* hB = sh[warp * 2 + 1];
#pragma unroll 4
        for (int k4 = 0; k4 < 16; k4++) {
            float4 qA = *(const float4*)&hA[k4 * 4];
            float4 qB = *(const float4*)&hB[k4 * 4];
            ull w0 = *(const ull*)&sW[(k4 * 4 + 0) * OC + c];
            ull w1 = *(const ull*)&sW[(k4 * 4 + 1) * OC + c];
            ull w2 = *(const ull*)&sW[(k4 * 4 + 2) * OC + c];
            ull w3 = *(const ull*)&sW[(k4 * 4 + 3) * OC + c];
            ffma2(accA, pack2(qA.x, qA.x), w0); ffma2(accB, pack2(qB.x, qB.x), w0);
            ffma2(accA, pack2(qA.y, qA.y), w1); ffma2(accB, pack2(qB.y, qB.y), w1);
            ffma2(accA, pack2(qA.z, qA.z), w2); ffma2(accB, pack2(qB.z, qB.z), w2);
            ffma2(accA, pack2(qA.w, qA.w), w3); ffma2(accB, pack2(qB.w, qB.w), w3);
        }
        float2 bl = *(const float2*)(blin + c);
        float oA0, oA1, oB0, oB1;
        unpack2(accA, oA0, oA1);
        unpack2(accB, oB0, oB1);
        *(float2*)(out + ((size_t)n0 << 6) + c)       = make_float2(oA0 + bl.x, oA1 + bl.y);
        *(float2*)(out + ((size_t)(n0 + 1) << 6) + c) = make_float2(oB0 + bl.x, oB1 + bl.y);
        __syncwarp();                                 // sh reuse guard for next pair
    }
}

// ---------------- launch ----------------
extern "C" void kernel_launch(void* const* d_in, const int* in_sizes, int n_in,
                              void* d_out, int out_size) {
    const float* x     = (const float*)d_in[0];
    const void*  ei    = d_in[1];
    const float* Wl    = (const float*)d_in[3];
    const float* Wr    = (const float*)d_in[4];
    const float* att   = (const float*)d_in[5];
    const float* bconv = (const float*)d_in[6];
    const float* Wlin  = (const float*)d_in[7];
    const float* blin  = (const float*)d_in[8];
    float* out = (float*)d_out;

    k_pre<<<196, 256>>>(Wl, Wr, Wlin, (const int*)ei);
    k_gh<<<GB + HB, 128>>>(x, ei);
    k_ss<<<SB + SCTB, 256>>>();
    k_aggr<<<296, 512>>>(att, bconv, blin, out);
}